// round 11
// baseline (speedup 1.0000x reference)
#include <cuda_runtime.h>
#include <cstdint>

// Problem dims (fixed by the reference).
#define L_DIM 8192
#define B_DIM 4096
#define D_DIM 1024

// Global accumulators / scratch (no allocation allowed).
__device__ double g_local_sum;
__device__ double g_glob_sum;
__device__ float  g_pos[B_DIM];

// ---------------------------------------------------------------------------
// PTX helpers
// ---------------------------------------------------------------------------
__device__ __forceinline__ uint32_t smem_u32(const void* p) {
    uint32_t a;
    asm("{ .reg .u64 t; cvta.to.shared.u64 t, %1; cvt.u32.u64 %0, t; }"
        : "=r"(a) : "l"(p));
    return a;
}

__device__ __forceinline__ void cp_async16(uint32_t dst, const void* src) {
    asm volatile("cp.async.cg.shared.global [%0], [%1], 16;"
                 :: "r"(dst), "l"(src) : "memory");
}
__device__ __forceinline__ void cp_commit() {
    asm volatile("cp.async.commit_group;" ::: "memory");
}
__device__ __forceinline__ void cp_wait1() {
    asm volatile("cp.async.wait_group 1;" ::: "memory");
}
__device__ __forceinline__ void cp_wait0() {
    asm volatile("cp.async.wait_group 0;" ::: "memory");
}

// ldmatrix x4: four 8x16B tiles -> 4 regs/thread. For f32 data this delivers
// the tf32 m16n8k8 fragment ownership pattern directly.
__device__ __forceinline__ void ldsm4(uint32_t* r, uint32_t addr) {
    asm volatile("ldmatrix.sync.aligned.m8n8.x4.shared.b16 {%0,%1,%2,%3}, [%4];"
                 : "=r"(r[0]), "=r"(r[1]), "=r"(r[2]), "=r"(r[3]) : "r"(addr));
}

// m16n8k8 tf32 MMA (baseline PTX, legacy-HMMA path on sm_103).
__device__ __forceinline__ void mma_tf32(float* c, const uint32_t* a,
                                         const uint32_t* b) {
    asm volatile(
        "mma.sync.aligned.m16n8k8.row.col.f32.tf32.tf32.f32 "
        "{%0,%1,%2,%3}, {%4,%5,%6,%7}, {%8,%9}, {%0,%1,%2,%3};"
        : "+f"(c[0]), "+f"(c[1]), "+f"(c[2]), "+f"(c[3])
        : "r"(a[0]), "r"(a[1]), "r"(a[2]), "r"(a[3]), "r"(b[0]), "r"(b[1]));
}

// ---------------------------------------------------------------------------
// init / local / pos / finalize
// ---------------------------------------------------------------------------
__global__ void init_kernel() {
    g_local_sum = 0.0;
    g_glob_sum  = 0.0;
}

__global__ void local_kernel(const float* __restrict__ qh,
                             const float* __restrict__ qr) {
    const size_t n4 = (size_t)L_DIM * D_DIM / 4;
    const float4* a4 = (const float4*)qh;
    const float4* b4 = (const float4*)qr;

    float s = 0.0f;
    for (size_t idx = (size_t)blockIdx.x * blockDim.x + threadIdx.x;
         idx < n4; idx += (size_t)gridDim.x * blockDim.x) {
        float4 a = a4[idx];
        float4 b = b4[idx];
        s += a.x * b.x + a.y * b.y + a.z * b.z + a.w * b.w;
    }
    for (int o = 16; o > 0; o >>= 1) s += __shfl_down_sync(0xffffffffu, s, o);

    __shared__ double red[8];
    int t = threadIdx.x;
    if ((t & 31) == 0) red[t >> 5] = (double)s;
    __syncthreads();
    if (t == 0) {
        double tot = 0.0;
        #pragma unroll
        for (int w = 0; w < 8; w++) tot += red[w];
        atomicAdd(&g_local_sum, tot);
    }
}

__global__ void pos_kernel(const float* __restrict__ pred,
                           const float* __restrict__ gt) {
    int i = blockIdx.x;
    int t = threadIdx.x;
    const float4* p4 = (const float4*)(pred + (size_t)i * D_DIM);
    const float4* g4 = (const float4*)(gt   + (size_t)i * D_DIM);
    float4 a = p4[t];
    float4 b = g4[t];
    float s = a.x * b.x + a.y * b.y + a.z * b.z + a.w * b.w;

    for (int o = 16; o > 0; o >>= 1) s += __shfl_down_sync(0xffffffffu, s, o);

    __shared__ float red[8];
    if ((t & 31) == 0) red[t >> 5] = s;
    __syncthreads();
    if (t == 0) {
        float tot = 0.0f;
        #pragma unroll
        for (int w = 0; w < 8; w++) tot += red[w];
        g_pos[i] = tot;
    }
}

// ---------------------------------------------------------------------------
// mma.sync tf32 NT-GEMM (scores = pred @ gt^T) + hinge + global reduce.
// CTA 128(i) x 256(j), BK=32 floats (128B rows, XOR-16B swizzle),
// 512 threads: 16 warps in 4x4 grid -> 32x64 warp tile, 64 accum/thread.
// 3-stage cp.async pipeline, ldmatrix x4 fragment feeds.
// ---------------------------------------------------------------------------
#define TM 128
#define TN 256
#define BKF 32
#define STAGE_A_BYTES (TM * 128)               // 16 KB
#define STAGE_B_BYTES (TN * 128)               // 32 KB
#define STAGE_BYTES   (STAGE_A_BYTES + STAGE_B_BYTES)
#define NSTAGE 3
#define DYN_SMEM (NSTAGE * STAGE_BYTES + 1024)
#define NKITERS (D_DIM / BKF)                  // 32

__device__ __forceinline__ void load_stage(uint32_t aBase, uint32_t bBase,
                                           const float* __restrict__ pred,
                                           const float* __restrict__ gt,
                                           int rowA0, int rowB0, int k0, int t) {
    // A: 128 rows x 8 chunks(16B) = 1024 chunks, 2/thread
    #pragma unroll
    for (int q = 0; q < 2; q++) {
        int idx = t + 512 * q;
        int row = idx >> 3;
        int c   = idx & 7;
        const float* src = pred + (size_t)(rowA0 + row) * D_DIM + k0 + c * 4;
        uint32_t dst = aBase + row * 128 + ((c ^ (row & 7)) << 4);
        cp_async16(dst, src);
    }
    // B: 256 rows x 8 chunks = 2048 chunks, 4/thread
    #pragma unroll
    for (int q = 0; q < 4; q++) {
        int idx = t + 512 * q;
        int row = idx >> 3;
        int c   = idx & 7;
        const float* src = gt + (size_t)(rowB0 + row) * D_DIM + k0 + c * 4;
        uint32_t dst = bBase + row * 128 + ((c ^ (row & 7)) << 4);
        cp_async16(dst, src);
    }
}

__global__ __launch_bounds__(512)
void gemm_hinge_mma(const float* __restrict__ pred, const float* __restrict__ gt) {
    extern __shared__ char dyn[];
    __shared__ double redsm[16];

    const int t    = threadIdx.x;
    const int wid  = t >> 5;
    const int lane = t & 31;
    const int wm   = wid & 3;    // warp row (4) -> 32 rows each
    const int wn   = wid >> 2;   // warp col (4) -> 64 cols each
    const int tg   = lane >> 2;  // groupID 0..7
    const int rowA0 = blockIdx.y * TM;   // pred rows (i)
    const int rowB0 = blockIdx.x * TN;   // gt rows   (j)

    const uint32_t dyn_base = (smem_u32(dyn) + 1023u) & ~1023u;

    // ldmatrix per-thread geometry: tile = lane>>3, tile-row = lane&7.
    const int trow = lane & 7;
    const int tlLo = (lane >> 3) & 1;   // tile&1
    const int tlHi = (lane >> 4) & 1;   // tile>>1
    // A x4 (mf): tiles {r+0,ch0},{r+8,ch0},{r+0,ch1},{r+8,ch1}
    int arow[2], axor[2];
    #pragma unroll
    for (int mf = 0; mf < 2; mf++) {
        int r = wm * 32 + mf * 16 + tlLo * 8 + trow;
        arow[mf] = r * 128;
        axor[mf] = r & 7;
    }
    const int aCadd = tlHi;
    // B x4 (nf pair p): tiles {n+0,ch0},{n+0,ch1},{n+8,ch0},{n+8,ch1}
    int brow[4], bxor[4];
    #pragma unroll
    for (int p = 0; p < 4; p++) {
        int r = wn * 64 + p * 16 + tlHi * 8 + trow;
        brow[p] = r * 128;
        bxor[p] = r & 7;
    }
    const int bCadd = tlLo;

    float c[2][8][4];
    #pragma unroll
    for (int mf = 0; mf < 2; mf++)
        #pragma unroll
        for (int nf = 0; nf < 8; nf++)
            #pragma unroll
            for (int r = 0; r < 4; r++) c[mf][nf][r] = 0.0f;

    // Prologue: prefetch stages 0, 1.
    load_stage(dyn_base,               dyn_base + STAGE_A_BYTES,
               pred, gt, rowA0, rowB0, 0, t);
    cp_commit();
    load_stage(dyn_base + STAGE_BYTES, dyn_base + STAGE_BYTES + STAGE_A_BYTES,
               pred, gt, rowA0, rowB0, BKF, t);
    cp_commit();

    for (int it = 0; it < NKITERS; ++it) {
        const uint32_t aBase = dyn_base + (it % NSTAGE) * STAGE_BYTES;
        const uint32_t bBase = aBase + STAGE_A_BYTES;

        if (it < NKITERS - 1) cp_wait1(); else cp_wait0();
        __syncthreads();  // stage `it` visible to all; stage (it+2)%3 free

        if (it + 2 < NKITERS) {
            const uint32_t la = dyn_base + ((it + 2) % NSTAGE) * STAGE_BYTES;
            load_stage(la, la + STAGE_A_BYTES, pred, gt, rowA0, rowB0,
                       (it + 2) * BKF, t);
            cp_commit();
        }

        #pragma unroll
        for (int ks = 0; ks < 4; ks++) {
            uint32_t a[2][4];
            #pragma unroll
            for (int mf = 0; mf < 2; mf++) {
                int ch = 2 * ks + aCadd;
                ldsm4(a[mf], aBase + arow[mf] + ((ch ^ axor[mf]) << 4));
            }
            uint32_t b[4][4];  // b[p] = {b0(nf=2p), b1(nf=2p), b0(2p+1), b1(2p+1)}
            #pragma unroll
            for (int p = 0; p < 4; p++) {
                int ch = 2 * ks + bCadd;
                ldsm4(b[p], bBase + brow[p] + ((ch ^ bxor[p]) << 4));
            }
            #pragma unroll
            for (int mf = 0; mf < 2; mf++)
                #pragma unroll
                for (int nf = 0; nf < 8; nf++)
                    mma_tf32(c[mf][nf], a[mf], b[nf >> 1] + (nf & 1) * 2);
        }
    }

    // Hinge epilogue straight from register accumulators.
    double acc = 0.0;
    #pragma unroll
    for (int mf = 0; mf < 2; mf++) {
        int r0 = rowA0 + wm * 32 + mf * 16 + tg;
        float p0 = 1.0f - g_pos[r0];
        float p1 = 1.0f - g_pos[r0 + 8];
        #pragma unroll
        for (int nf = 0; nf < 8; nf++) {
            float v0 = c[mf][nf][0] + p0;
            float v1 = c[mf][nf][1] + p0;
            float v2 = c[mf][nf][2] + p1;
            float v3 = c[mf][nf][3] + p1;
            if (v0 > 0.0f) acc += (double)v0;
            if (v1 > 0.0f) acc += (double)v1;
            if (v2 > 0.0f) acc += (double)v2;
            if (v3 > 0.0f) acc += (double)v3;
        }
    }

    for (int o = 16; o > 0; o >>= 1)
        acc += __shfl_down_sync(0xffffffffu, acc, o);
    if (lane == 0) redsm[wid] = acc;
    __syncthreads();
    if (t == 0) {
        double tot = 0.0;
        #pragma unroll
        for (int w = 0; w < 16; w++) tot += redsm[w];
        atomicAdd(&g_glob_sum, tot);
    }
}

// ---------------------------------------------------------------------------
__global__ void finalize_kernel(float* __restrict__ out) {
    out[0] = (float)(g_glob_sum - g_local_sum / (double)L_DIM);
}

// ---------------------------------------------------------------------------
extern "C" void kernel_launch(void* const* d_in, const int* in_sizes, int n_in,
                              void* d_out, int out_size) {
    (void)in_sizes; (void)n_in; (void)out_size;
    const float* q_hat  = (const float*)d_in[0];
    const float* q_real = (const float*)d_in[1];
    const float* gt     = (const float*)d_in[2];  // encoded_gt   [B, D]
    const float* pred   = (const float*)d_in[3];  // encoded_pred [B, D]
    float* out = (float*)d_out;

    cudaFuncSetAttribute(gemm_hinge_mma,
                         cudaFuncAttributeMaxDynamicSharedMemorySize, DYN_SMEM);

    init_kernel<<<1, 1>>>();
    local_kernel<<<2048, 256>>>(q_hat, q_real);
    pos_kernel<<<B_DIM, 256>>>(pred, gt);
    dim3 grid(B_DIM / TN, B_DIM / TM);  // (16 j-tiles, 32 i-tiles)
    gemm_hinge_mma<<<grid, 512, DYN_SMEM>>>(pred, gt);
    finalize_kernel<<<1, 1>>>(out);
}

// round 12
// speedup vs baseline: 1.4454x; 1.4454x over previous
#include <cuda_runtime.h>
#include <cuda_fp16.h>
#include <cstdint>

// Problem dims (fixed by the reference).
#define L_DIM 8192
#define B_DIM 4096
#define D_DIM 1024

// Global accumulators / scratch (no allocation allowed).
__device__ double g_local_sum;
__device__ double g_glob_sum;
__device__ float  g_pos[B_DIM];
__device__ __half g_pred_h[B_DIM * D_DIM];   // fp16 copies for the tensor GEMM
__device__ __half g_gt_h[B_DIM * D_DIM];

// ---------------------------------------------------------------------------
// PTX helpers
// ---------------------------------------------------------------------------
__device__ __forceinline__ uint32_t smem_u32(const void* p) {
    uint32_t a;
    asm("{ .reg .u64 t; cvta.to.shared.u64 t, %1; cvt.u32.u64 %0, t; }"
        : "=r"(a) : "l"(p));
    return a;
}

__device__ __forceinline__ void cp_async16(uint32_t dst, const void* src) {
    asm volatile("cp.async.cg.shared.global [%0], [%1], 16;"
                 :: "r"(dst), "l"(src) : "memory");
}
__device__ __forceinline__ void cp_commit() {
    asm volatile("cp.async.commit_group;" ::: "memory");
}
__device__ __forceinline__ void cp_wait1() {
    asm volatile("cp.async.wait_group 1;" ::: "memory");
}
__device__ __forceinline__ void cp_wait0() {
    asm volatile("cp.async.wait_group 0;" ::: "memory");
}

// ldmatrix x4: four 8x(8 b16) tiles -> 4 regs/thread (native b16 fragments).
__device__ __forceinline__ void ldsm4(uint32_t* r, uint32_t addr) {
    asm volatile("ldmatrix.sync.aligned.m8n8.x4.shared.b16 {%0,%1,%2,%3}, [%4];"
                 : "=r"(r[0]), "=r"(r[1]), "=r"(r[2]), "=r"(r[3]) : "r"(addr));
}

// m16n8k16 fp16 MMA, fp32 accumulate (2048 MACs per instruction).
__device__ __forceinline__ void mma_f16(float* c, const uint32_t* a,
                                        const uint32_t* b) {
    asm volatile(
        "mma.sync.aligned.m16n8k16.row.col.f32.f16.f16.f32 "
        "{%0,%1,%2,%3}, {%4,%5,%6,%7}, {%8,%9}, {%0,%1,%2,%3};"
        : "+f"(c[0]), "+f"(c[1]), "+f"(c[2]), "+f"(c[3])
        : "r"(a[0]), "r"(a[1]), "r"(a[2]), "r"(a[3]), "r"(b[0]), "r"(b[1]));
}

// ---------------------------------------------------------------------------
// init / convert / local / pos / finalize
// ---------------------------------------------------------------------------
__global__ void init_kernel() {
    g_local_sum = 0.0;
    g_glob_sum  = 0.0;
}

// f32 -> f16 conversion of pred and gt (vectorized: float4 -> half2 x2).
__global__ void convert_kernel(const float* __restrict__ pred,
                               const float* __restrict__ gt) {
    const size_t n4 = (size_t)B_DIM * D_DIM / 4;
    const float4* p4 = (const float4*)pred;
    const float4* g4 = (const float4*)gt;
    __half2* ph = (__half2*)g_pred_h;
    __half2* gh = (__half2*)g_gt_h;
    for (size_t i = (size_t)blockIdx.x * blockDim.x + threadIdx.x;
         i < n4; i += (size_t)gridDim.x * blockDim.x) {
        float4 a = p4[i];
        float4 b = g4[i];
        ph[2 * i]     = __floats2half2_rn(a.x, a.y);
        ph[2 * i + 1] = __floats2half2_rn(a.z, a.w);
        gh[2 * i]     = __floats2half2_rn(b.x, b.y);
        gh[2 * i + 1] = __floats2half2_rn(b.z, b.w);
    }
}

__global__ void local_kernel(const float* __restrict__ qh,
                             const float* __restrict__ qr) {
    const size_t n4 = (size_t)L_DIM * D_DIM / 4;
    const float4* a4 = (const float4*)qh;
    const float4* b4 = (const float4*)qr;

    float s = 0.0f;
    for (size_t idx = (size_t)blockIdx.x * blockDim.x + threadIdx.x;
         idx < n4; idx += (size_t)gridDim.x * blockDim.x) {
        float4 a = a4[idx];
        float4 b = b4[idx];
        s += a.x * b.x + a.y * b.y + a.z * b.z + a.w * b.w;
    }
    for (int o = 16; o > 0; o >>= 1) s += __shfl_down_sync(0xffffffffu, s, o);

    __shared__ double red[8];
    int t = threadIdx.x;
    if ((t & 31) == 0) red[t >> 5] = (double)s;
    __syncthreads();
    if (t == 0) {
        double tot = 0.0;
        #pragma unroll
        for (int w = 0; w < 8; w++) tot += red[w];
        atomicAdd(&g_local_sum, tot);
    }
}

__global__ void pos_kernel(const float* __restrict__ pred,
                           const float* __restrict__ gt) {
    int i = blockIdx.x;
    int t = threadIdx.x;
    const float4* p4 = (const float4*)(pred + (size_t)i * D_DIM);
    const float4* g4 = (const float4*)(gt   + (size_t)i * D_DIM);
    float4 a = p4[t];
    float4 b = g4[t];
    float s = a.x * b.x + a.y * b.y + a.z * b.z + a.w * b.w;

    for (int o = 16; o > 0; o >>= 1) s += __shfl_down_sync(0xffffffffu, s, o);

    __shared__ float red[8];
    if ((t & 31) == 0) red[t >> 5] = s;
    __syncthreads();
    if (t == 0) {
        float tot = 0.0f;
        #pragma unroll
        for (int w = 0; w < 8; w++) tot += red[w];
        g_pos[i] = tot;
    }
}

// ---------------------------------------------------------------------------
// fp16 mma.sync NT-GEMM (scores = pred @ gt^T) + hinge + global reduce.
// CTA 128(i) x 256(j). BK=64 halfs (128B rows, XOR-16B swizzle).
// 8 warps 2x4 (64x64 warp tile), 3-stage cp.async, ldmatrix x4 feeds.
// ---------------------------------------------------------------------------
#define TM 128
#define TN 256
#define BKH 64                                 // halfs per k-slab (128 B)
#define STAGE_A_BYTES (TM * 128)               // 16 KB
#define STAGE_B_BYTES (TN * 128)               // 32 KB
#define STAGE_BYTES   (STAGE_A_BYTES + STAGE_B_BYTES)
#define NSTAGE 3
#define DYN_SMEM (NSTAGE * STAGE_BYTES + 1024)
#define NKITERS (D_DIM / BKH)                  // 16

__device__ __forceinline__ void load_stage(uint32_t aBase, uint32_t bBase,
                                           const __half* __restrict__ predh,
                                           const __half* __restrict__ gth,
                                           int rowA0, int rowB0, int k0, int t) {
    // A: 128 rows x 8 chunks(16B = 8 halfs) = 1024 chunks, 4/thread
    #pragma unroll
    for (int q = 0; q < 4; q++) {
        int idx = t + 256 * q;
        int row = idx >> 3;
        int c   = idx & 7;
        const __half* src = predh + (size_t)(rowA0 + row) * D_DIM + k0 + c * 8;
        uint32_t dst = aBase + row * 128 + ((c ^ (row & 7)) << 4);
        cp_async16(dst, src);
    }
    // B: 256 rows x 8 chunks = 2048 chunks, 8/thread
    #pragma unroll
    for (int q = 0; q < 8; q++) {
        int idx = t + 256 * q;
        int row = idx >> 3;
        int c   = idx & 7;
        const __half* src = gth + (size_t)(rowB0 + row) * D_DIM + k0 + c * 8;
        uint32_t dst = bBase + row * 128 + ((c ^ (row & 7)) << 4);
        cp_async16(dst, src);
    }
}

__global__ __launch_bounds__(256)
void gemm_hinge_mma(void) {
    extern __shared__ char dyn[];
    __shared__ double redsm[8];

    const __half* predh = g_pred_h;
    const __half* gth   = g_gt_h;

    const int t    = threadIdx.x;
    const int wid  = t >> 5;
    const int lane = t & 31;
    const int wm   = wid & 1;    // warp row (2) -> 64 rows
    const int wn   = wid >> 1;   // warp col (4) -> 64 cols
    const int tg   = lane >> 2;  // groupID 0..7
    const int rowA0 = blockIdx.y * TM;   // pred rows (i)
    const int rowB0 = blockIdx.x * TN;   // gt rows   (j)

    const uint32_t dyn_base = (smem_u32(dyn) + 1023u) & ~1023u;

    // ldmatrix per-thread geometry: tile = lane>>3, tile-row = lane&7.
    const int trow = lane & 7;
    const int tlLo = (lane >> 3) & 1;   // tile&1
    const int tlHi = (lane >> 4) & 1;   // tile>>1
    // A x4 (mf): tiles {r,ch0},{r+8,ch0},{r,ch1},{r+8,ch1}  (= a0..a3 of k16)
    int arow[4], axor[4];
    #pragma unroll
    for (int mf = 0; mf < 4; mf++) {
        int r = wm * 64 + mf * 16 + tlLo * 8 + trow;
        arow[mf] = r * 128;
        axor[mf] = r & 7;
    }
    const int aCadd = tlHi;
    // B x4 (nf pair p): tiles {n,ch0},{n,ch1},{n+8,ch0},{n+8,ch1}
    int brow[4], bxor[4];
    #pragma unroll
    for (int p = 0; p < 4; p++) {
        int r = wn * 64 + p * 16 + tlHi * 8 + trow;
        brow[p] = r * 128;
        bxor[p] = r & 7;
    }
    const int bCadd = tlLo;

    float c[4][8][4];
    #pragma unroll
    for (int mf = 0; mf < 4; mf++)
        #pragma unroll
        for (int nf = 0; nf < 8; nf++)
            #pragma unroll
            for (int r = 0; r < 4; r++) c[mf][nf][r] = 0.0f;

    // Prologue: prefetch stages 0, 1.
    load_stage(dyn_base,               dyn_base + STAGE_A_BYTES,
               predh, gth, rowA0, rowB0, 0, t);
    cp_commit();
    load_stage(dyn_base + STAGE_BYTES, dyn_base + STAGE_BYTES + STAGE_A_BYTES,
               predh, gth, rowA0, rowB0, BKH, t);
    cp_commit();

    for (int it = 0; it < NKITERS; ++it) {
        const uint32_t aBase = dyn_base + (it % NSTAGE) * STAGE_BYTES;
        const uint32_t bBase = aBase + STAGE_A_BYTES;

        if (it < NKITERS - 1) cp_wait1(); else cp_wait0();
        __syncthreads();  // stage `it` visible to all; stage (it+2)%3 free

        if (it + 2 < NKITERS) {
            const uint32_t la = dyn_base + ((it + 2) % NSTAGE) * STAGE_BYTES;
            load_stage(la, la + STAGE_A_BYTES, predh, gth, rowA0, rowB0,
                       (it + 2) * BKH, t);
            cp_commit();
        }

        // 4 k-steps of 16 halfs (2 chunks of 16B each)
        #pragma unroll
        for (int ks = 0; ks < 4; ks++) {
            uint32_t a[4][4];
            #pragma unroll
            for (int mf = 0; mf < 4; mf++) {
                int ch = 2 * ks + aCadd;
                ldsm4(a[mf], aBase + arow[mf] + ((ch ^ axor[mf]) << 4));
            }
            uint32_t b[4][4];  // b[p] = {b0(nf=2p), b1(nf=2p), b0(2p+1), b1(2p+1)}
            #pragma unroll
            for (int p = 0; p < 4; p++) {
                int ch = 2 * ks + bCadd;
                ldsm4(b[p], bBase + brow[p] + ((ch ^ bxor[p]) << 4));
            }
            #pragma unroll
            for (int mf = 0; mf < 4; mf++)
                #pragma unroll
                for (int nf = 0; nf < 8; nf++)
                    mma_f16(c[mf][nf], a[mf], b[nf >> 1] + (nf & 1) * 2);
        }
    }

    // Hinge epilogue straight from register accumulators.
    double acc = 0.0;
    #pragma unroll
    for (int mf = 0; mf < 4; mf++) {
        int r0 = rowA0 + wm * 64 + mf * 16 + tg;
        float p0 = 1.0f - g_pos[r0];
        float p1 = 1.0f - g_pos[r0 + 8];
        #pragma unroll
        for (int nf = 0; nf < 8; nf++) {
            float v0 = c[mf][nf][0] + p0;
            float v1 = c[mf][nf][1] + p0;
            float v2 = c[mf][nf][2] + p1;
            float v3 = c[mf][nf][3] + p1;
            if (v0 > 0.0f) acc += (double)v0;
            if (v1 > 0.0f) acc += (double)v1;
            if (v2 > 0.0f) acc += (double)v2;
            if (v3 > 0.0f) acc += (double)v3;
        }
    }

    for (int o = 16; o > 0; o >>= 1)
        acc += __shfl_down_sync(0xffffffffu, acc, o);
    if (lane == 0) redsm[wid] = acc;
    __syncthreads();
    if (t == 0) {
        double tot = 0.0;
        #pragma unroll
        for (int w = 0; w < 8; w++) tot += redsm[w];
        atomicAdd(&g_glob_sum, tot);
    }
}

// ---------------------------------------------------------------------------
__global__ void finalize_kernel(float* __restrict__ out) {
    out[0] = (float)(g_glob_sum - g_local_sum / (double)L_DIM);
}

// ---------------------------------------------------------------------------
extern "C" void kernel_launch(void* const* d_in, const int* in_sizes, int n_in,
                              void* d_out, int out_size) {
    (void)in_sizes; (void)n_in; (void)out_size;
    const float* q_hat  = (const float*)d_in[0];
    const float* q_real = (const float*)d_in[1];
    const float* gt     = (const float*)d_in[2];  // encoded_gt   [B, D]
    const float* pred   = (const float*)d_in[3];  // encoded_pred [B, D]
    float* out = (float*)d_out;

    cudaFuncSetAttribute(gemm_hinge_mma,
                         cudaFuncAttributeMaxDynamicSharedMemorySize, DYN_SMEM);

    init_kernel<<<1, 1>>>();
    convert_kernel<<<1024, 256>>>(pred, gt);
    local_kernel<<<2048, 256>>>(q_hat, q_real);
    pos_kernel<<<B_DIM, 256>>>(pred, gt);
    dim3 grid(B_DIM / TN, B_DIM / TM);  // (16 j-tiles, 32 i-tiles)
    gemm_hinge_mma<<<grid, 256, DYN_SMEM>>>();
    finalize_kernel<<<1, 1>>>(out);
}

// round 13
// speedup vs baseline: 1.4672x; 1.0150x over previous
#include <cuda_runtime.h>
#include <cuda_fp16.h>
#include <cstdint>

// Problem dims (fixed by the reference).
#define L_DIM 8192
#define B_DIM 4096
#define D_DIM 1024

// Global accumulators / scratch (no allocation allowed).
__device__ double g_local_sum;
__device__ double g_glob_sum;
__device__ float  g_pos[B_DIM];
__device__ __half g_pred_h[B_DIM * D_DIM];   // fp16 copies for the tensor GEMM
__device__ __half g_gt_h[B_DIM * D_DIM];

// ---------------------------------------------------------------------------
// PTX helpers
// ---------------------------------------------------------------------------
__device__ __forceinline__ uint32_t smem_u32(const void* p) {
    uint32_t a;
    asm("{ .reg .u64 t; cvta.to.shared.u64 t, %1; cvt.u32.u64 %0, t; }"
        : "=r"(a) : "l"(p));
    return a;
}

__device__ __forceinline__ void cp_async16(uint32_t dst, const void* src) {
    asm volatile("cp.async.cg.shared.global [%0], [%1], 16;"
                 :: "r"(dst), "l"(src) : "memory");
}
__device__ __forceinline__ void cp_commit() {
    asm volatile("cp.async.commit_group;" ::: "memory");
}
__device__ __forceinline__ void cp_wait1() {
    asm volatile("cp.async.wait_group 1;" ::: "memory");
}
__device__ __forceinline__ void cp_wait0() {
    asm volatile("cp.async.wait_group 0;" ::: "memory");
}

// ldmatrix x4: four 8x(8 b16) tiles -> 4 regs/thread (native b16 fragments).
__device__ __forceinline__ void ldsm4(uint32_t* r, uint32_t addr) {
    asm volatile("ldmatrix.sync.aligned.m8n8.x4.shared.b16 {%0,%1,%2,%3}, [%4];"
                 : "=r"(r[0]), "=r"(r[1]), "=r"(r[2]), "=r"(r[3]) : "r"(addr));
}

// m16n8k16 fp16 MMA, fp32 accumulate (2048 MACs per instruction).
__device__ __forceinline__ void mma_f16(float* c, const uint32_t* a,
                                        const uint32_t* b) {
    asm volatile(
        "mma.sync.aligned.m16n8k16.row.col.f32.f16.f16.f32 "
        "{%0,%1,%2,%3}, {%4,%5,%6,%7}, {%8,%9}, {%0,%1,%2,%3};"
        : "+f"(c[0]), "+f"(c[1]), "+f"(c[2]), "+f"(c[3])
        : "r"(a[0]), "r"(a[1]), "r"(a[2]), "r"(a[3]), "r"(b[0]), "r"(b[1]));
}

// ---------------------------------------------------------------------------
// prep: zero accumulators (block 0), convert pred/gt row i to fp16, and
// compute g_pos[i] = dot(pred[i], gt[i]) — one pass over the 32 MB.
// ---------------------------------------------------------------------------
__global__ void prep_kernel(const float* __restrict__ pred,
                            const float* __restrict__ gt) {
    const int i = blockIdx.x;
    const int t = threadIdx.x;  // 0..255, D/4 = 256 float4 per row

    if (i == 0 && t == 0) {
        g_local_sum = 0.0;
        g_glob_sum  = 0.0;
    }

    const float4* p4 = (const float4*)(pred + (size_t)i * D_DIM);
    const float4* g4 = (const float4*)(gt   + (size_t)i * D_DIM);
    float4 a = p4[t];
    float4 b = g4[t];

    __half2* ph = (__half2*)(g_pred_h + (size_t)i * D_DIM);
    __half2* gh = (__half2*)(g_gt_h   + (size_t)i * D_DIM);
    ph[2 * t]     = __floats2half2_rn(a.x, a.y);
    ph[2 * t + 1] = __floats2half2_rn(a.z, a.w);
    gh[2 * t]     = __floats2half2_rn(b.x, b.y);
    gh[2 * t + 1] = __floats2half2_rn(b.z, b.w);

    float s = a.x * b.x + a.y * b.y + a.z * b.z + a.w * b.w;
    for (int o = 16; o > 0; o >>= 1) s += __shfl_down_sync(0xffffffffu, s, o);

    __shared__ float red[8];
    if ((t & 31) == 0) red[t >> 5] = s;
    __syncthreads();
    if (t == 0) {
        float tot = 0.0f;
        #pragma unroll
        for (int w = 0; w < 8; w++) tot += red[w];
        g_pos[i] = tot;
    }
}

// ---------------------------------------------------------------------------
// local loss: sum(q_hat * q_real) over 8.4M elements (HBM-bound)
// ---------------------------------------------------------------------------
__global__ void local_kernel(const float* __restrict__ qh,
                             const float* __restrict__ qr) {
    const size_t n4 = (size_t)L_DIM * D_DIM / 4;
    const float4* a4 = (const float4*)qh;
    const float4* b4 = (const float4*)qr;

    float s = 0.0f;
    for (size_t idx = (size_t)blockIdx.x * blockDim.x + threadIdx.x;
         idx < n4; idx += (size_t)gridDim.x * blockDim.x) {
        float4 a = a4[idx];
        float4 b = b4[idx];
        s += a.x * b.x + a.y * b.y + a.z * b.z + a.w * b.w;
    }
    for (int o = 16; o > 0; o >>= 1) s += __shfl_down_sync(0xffffffffu, s, o);

    __shared__ double red[8];
    int t = threadIdx.x;
    if ((t & 31) == 0) red[t >> 5] = (double)s;
    __syncthreads();
    if (t == 0) {
        double tot = 0.0;
        #pragma unroll
        for (int w = 0; w < 8; w++) tot += red[w];
        atomicAdd(&g_local_sum, tot);
    }
}

// ---------------------------------------------------------------------------
// fp16 mma.sync NT-GEMM (scores = pred @ gt^T) + hinge + global reduce.
// CTA 128(i) x 256(j). BK=64 halfs (128B rows, XOR-16B swizzle).
// 512 threads: 16 warps in 4x4 grid -> 32x64 warp tile, 64 accum/thread.
// 3-stage cp.async pipeline, ldmatrix x4 feeds.
// ---------------------------------------------------------------------------
#define TM 128
#define TN 256
#define BKH 64                                 // halfs per k-slab (128 B)
#define STAGE_A_BYTES (TM * 128)               // 16 KB
#define STAGE_B_BYTES (TN * 128)               // 32 KB
#define STAGE_BYTES   (STAGE_A_BYTES + STAGE_B_BYTES)
#define NSTAGE 3
#define DYN_SMEM (NSTAGE * STAGE_BYTES + 1024)
#define NKITERS (D_DIM / BKH)                  // 16

__device__ __forceinline__ void load_stage(uint32_t aBase, uint32_t bBase,
                                           const __half* __restrict__ predh,
                                           const __half* __restrict__ gth,
                                           int rowA0, int rowB0, int k0, int t) {
    // A: 128 rows x 8 chunks(16B = 8 halfs) = 1024 chunks, 2/thread
    #pragma unroll
    for (int q = 0; q < 2; q++) {
        int idx = t + 512 * q;
        int row = idx >> 3;
        int c   = idx & 7;
        const __half* src = predh + (size_t)(rowA0 + row) * D_DIM + k0 + c * 8;
        uint32_t dst = aBase + row * 128 + ((c ^ (row & 7)) << 4);
        cp_async16(dst, src);
    }
    // B: 256 rows x 8 chunks = 2048 chunks, 4/thread
    #pragma unroll
    for (int q = 0; q < 4; q++) {
        int idx = t + 512 * q;
        int row = idx >> 3;
        int c   = idx & 7;
        const __half* src = gth + (size_t)(rowB0 + row) * D_DIM + k0 + c * 8;
        uint32_t dst = bBase + row * 128 + ((c ^ (row & 7)) << 4);
        cp_async16(dst, src);
    }
}

__global__ __launch_bounds__(512)
void gemm_hinge_mma(void) {
    extern __shared__ char dyn[];
    __shared__ double redsm[16];

    const __half* predh = g_pred_h;
    const __half* gth   = g_gt_h;

    const int t    = threadIdx.x;
    const int wid  = t >> 5;
    const int lane = t & 31;
    const int wm   = wid & 3;    // warp row (4) -> 32 rows each
    const int wn   = wid >> 2;   // warp col (4) -> 64 cols each
    const int tg   = lane >> 2;  // groupID 0..7
    const int rowA0 = blockIdx.y * TM;   // pred rows (i)
    const int rowB0 = blockIdx.x * TN;   // gt rows   (j)

    const uint32_t dyn_base = (smem_u32(dyn) + 1023u) & ~1023u;

    // ldmatrix per-thread geometry: tile = lane>>3, tile-row = lane&7.
    const int trow = lane & 7;
    const int tlLo = (lane >> 3) & 1;   // tile&1
    const int tlHi = (lane >> 4) & 1;   // tile>>1
    // A x4 (mf): tiles {r,ch0},{r+8,ch0},{r,ch1},{r+8,ch1}  (= a0..a3 of k16)
    int arow[2], axor[2];
    #pragma unroll
    for (int mf = 0; mf < 2; mf++) {
        int r = wm * 32 + mf * 16 + tlLo * 8 + trow;
        arow[mf] = r * 128;
        axor[mf] = r & 7;
    }
    const int aCadd = tlHi;
    // B x4 (nf pair p): tiles {n,ch0},{n,ch1},{n+8,ch0},{n+8,ch1}
    int brow[4], bxor[4];
    #pragma unroll
    for (int p = 0; p < 4; p++) {
        int r = wn * 64 + p * 16 + tlHi * 8 + trow;
        brow[p] = r * 128;
        bxor[p] = r & 7;
    }
    const int bCadd = tlLo;

    float c[2][8][4];
    #pragma unroll
    for (int mf = 0; mf < 2; mf++)
        #pragma unroll
        for (int nf = 0; nf < 8; nf++)
            #pragma unroll
            for (int r = 0; r < 4; r++) c[mf][nf][r] = 0.0f;

    // Prologue: prefetch stages 0, 1.
    load_stage(dyn_base,               dyn_base + STAGE_A_BYTES,
               predh, gth, rowA0, rowB0, 0, t);
    cp_commit();
    load_stage(dyn_base + STAGE_BYTES, dyn_base + STAGE_BYTES + STAGE_A_BYTES,
               predh, gth, rowA0, rowB0, BKH, t);
    cp_commit();

    for (int it = 0; it < NKITERS; ++it) {
        const uint32_t aBase = dyn_base + (it % NSTAGE) * STAGE_BYTES;
        const uint32_t bBase = aBase + STAGE_A_BYTES;

        if (it < NKITERS - 1) cp_wait1(); else cp_wait0();
        __syncthreads();  // stage `it` visible to all; stage (it+2)%3 free

        if (it + 2 < NKITERS) {
            const uint32_t la = dyn_base + ((it + 2) % NSTAGE) * STAGE_BYTES;
            load_stage(la, la + STAGE_A_BYTES, predh, gth, rowA0, rowB0,
                       (it + 2) * BKH, t);
            cp_commit();
        }

        // 4 k-steps of 16 halfs (2 chunks of 16B each)
        #pragma unroll
        for (int ks = 0; ks < 4; ks++) {
            uint32_t a[2][4];
            #pragma unroll
            for (int mf = 0; mf < 2; mf++) {
                int ch = 2 * ks + aCadd;
                ldsm4(a[mf], aBase + arow[mf] + ((ch ^ axor[mf]) << 4));
            }
            uint32_t b[4][4];  // b[p] = {b0(nf=2p), b1(nf=2p), b0(2p+1), b1(2p+1)}
            #pragma unroll
            for (int p = 0; p < 4; p++) {
                int ch = 2 * ks + bCadd;
                ldsm4(b[p], bBase + brow[p] + ((ch ^ bxor[p]) << 4));
            }
            #pragma unroll
            for (int mf = 0; mf < 2; mf++)
                #pragma unroll
                for (int nf = 0; nf < 8; nf++)
                    mma_f16(c[mf][nf], a[mf], b[nf >> 1] + (nf & 1) * 2);
        }
    }

    // Hinge epilogue straight from register accumulators.
    double acc = 0.0;
    #pragma unroll
    for (int mf = 0; mf < 2; mf++) {
        int r0 = rowA0 + wm * 32 + mf * 16 + tg;
        float p0 = 1.0f - g_pos[r0];
        float p1 = 1.0f - g_pos[r0 + 8];
        #pragma unroll
        for (int nf = 0; nf < 8; nf++) {
            float v0 = c[mf][nf][0] + p0;
            float v1 = c[mf][nf][1] + p0;
            float v2 = c[mf][nf][2] + p1;
            float v3 = c[mf][nf][3] + p1;
            if (v0 > 0.0f) acc += (double)v0;
            if (v1 > 0.0f) acc += (double)v1;
            if (v2 > 0.0f) acc += (double)v2;
            if (v3 > 0.0f) acc += (double)v3;
        }
    }

    for (int o = 16; o > 0; o >>= 1)
        acc += __shfl_down_sync(0xffffffffu, acc, o);
    if (lane == 0) redsm[wid] = acc;
    __syncthreads();
    if (t == 0) {
        double tot = 0.0;
        #pragma unroll
        for (int w = 0; w < 16; w++) tot += redsm[w];
        atomicAdd(&g_glob_sum, tot);
    }
}

// ---------------------------------------------------------------------------
__global__ void finalize_kernel(float* __restrict__ out) {
    out[0] = (float)(g_glob_sum - g_local_sum / (double)L_DIM);
}

// ---------------------------------------------------------------------------
extern "C" void kernel_launch(void* const* d_in, const int* in_sizes, int n_in,
                              void* d_out, int out_size) {
    (void)in_sizes; (void)n_in; (void)out_size;
    const float* q_hat  = (const float*)d_in[0];
    const float* q_real = (const float*)d_in[1];
    const float* gt     = (const float*)d_in[2];  // encoded_gt   [B, D]
    const float* pred   = (const float*)d_in[3];  // encoded_pred [B, D]
    float* out = (float*)d_out;

    cudaFuncSetAttribute(gemm_hinge_mma,
                         cudaFuncAttributeMaxDynamicSharedMemorySize, DYN_SMEM);

    prep_kernel<<<B_DIM, 256>>>(pred, gt);        // init + convert + pos, fused
    local_kernel<<<2048, 256>>>(q_hat, q_real);
    dim3 grid(B_DIM / TN, B_DIM / TM);  // (16 j-tiles, 32 i-tiles)
    gemm_hinge_mma<<<grid, 512, DYN_SMEM>>>();
    finalize_kernel<<<1, 1>>>(out);
}

// round 15
// speedup vs baseline: 2.1598x; 1.4721x over previous
#include <cuda_runtime.h>
#include <cuda_fp16.h>
#include <cstdint>

// Problem dims (fixed by the reference).
#define L_DIM 8192
#define B_DIM 4096
#define D_DIM 1024

// Global accumulators / scratch (no allocation allowed).
__device__ double g_local_sum;
__device__ double g_glob_sum;
__device__ unsigned int g_done_ctas;
__device__ float  g_pos[B_DIM];
__device__ __half g_pred_h[B_DIM * D_DIM];   // fp16 copies for the tensor GEMM
__device__ __half g_gt_h[B_DIM * D_DIM];

// ---------------------------------------------------------------------------
// PTX helpers
// ---------------------------------------------------------------------------
__device__ __forceinline__ uint32_t smem_u32(const void* p) {
    uint32_t a;
    asm("{ .reg .u64 t; cvta.to.shared.u64 t, %1; cvt.u32.u64 %0, t; }"
        : "=r"(a) : "l"(p));
    return a;
}

__device__ __forceinline__ void cp_async16(uint32_t dst, const void* src) {
    asm volatile("cp.async.cg.shared.global [%0], [%1], 16;"
                 :: "r"(dst), "l"(src) : "memory");
}
__device__ __forceinline__ void cp_commit() {
    asm volatile("cp.async.commit_group;" ::: "memory");
}
__device__ __forceinline__ void cp_wait1() {
    asm volatile("cp.async.wait_group 1;" ::: "memory");
}
__device__ __forceinline__ void cp_wait0() {
    asm volatile("cp.async.wait_group 0;" ::: "memory");
}

// ldmatrix x4: four 8x(8 b16) tiles -> 4 regs/thread (native b16 fragments).
__device__ __forceinline__ void ldsm4(uint32_t* r, uint32_t addr) {
    asm volatile("ldmatrix.sync.aligned.m8n8.x4.shared.b16 {%0,%1,%2,%3}, [%4];"
                 : "=r"(r[0]), "=r"(r[1]), "=r"(r[2]), "=r"(r[3]) : "r"(addr));
}

// m16n8k16 fp16 MMA, fp32 accumulate (2048 MACs per instruction).
__device__ __forceinline__ void mma_f16(float* c, const uint32_t* a,
                                        const uint32_t* b) {
    asm volatile(
        "mma.sync.aligned.m16n8k16.row.col.f32.f16.f16.f32 "
        "{%0,%1,%2,%3}, {%4,%5,%6,%7}, {%8,%9}, {%0,%1,%2,%3};"
        : "+f"(c[0]), "+f"(c[1]), "+f"(c[2]), "+f"(c[3])
        : "r"(a[0]), "r"(a[1]), "r"(a[2]), "r"(a[3]), "r"(b[0]), "r"(b[1]));
}

// ---------------------------------------------------------------------------
// prep: zero accumulators (block 0), convert pred/gt row i to fp16, and
// compute g_pos[i] = dot(pred[i], gt[i]) — one pass over the 32 MB.
// ---------------------------------------------------------------------------
__global__ void prep_kernel(const float* __restrict__ pred,
                            const float* __restrict__ gt) {
    const int i = blockIdx.x;
    const int t = threadIdx.x;  // 0..255, D/4 = 256 float4 per row

    if (i == 0 && t == 0) {
        g_local_sum = 0.0;
        g_glob_sum  = 0.0;
        g_done_ctas = 0u;
    }

    const float4* p4 = (const float4*)(pred + (size_t)i * D_DIM);
    const float4* g4 = (const float4*)(gt   + (size_t)i * D_DIM);
    float4 a = p4[t];
    float4 b = g4[t];

    __half2* ph = (__half2*)(g_pred_h + (size_t)i * D_DIM);
    __half2* gh = (__half2*)(g_gt_h   + (size_t)i * D_DIM);
    ph[2 * t]     = __floats2half2_rn(a.x, a.y);
    ph[2 * t + 1] = __floats2half2_rn(a.z, a.w);
    gh[2 * t]     = __floats2half2_rn(b.x, b.y);
    gh[2 * t + 1] = __floats2half2_rn(b.z, b.w);

    float s = a.x * b.x + a.y * b.y + a.z * b.z + a.w * b.w;
    for (int o = 16; o > 0; o >>= 1) s += __shfl_down_sync(0xffffffffu, s, o);

    __shared__ float red[8];
    if ((t & 31) == 0) red[t >> 5] = s;
    __syncthreads();
    if (t == 0) {
        float tot = 0.0f;
        #pragma unroll
        for (int w = 0; w < 8; w++) tot += red[w];
        g_pos[i] = tot;
    }
}

// ---------------------------------------------------------------------------
// local loss: sum(q_hat * q_real) over 8.4M elements (HBM-bound)
// ---------------------------------------------------------------------------
__global__ void local_kernel(const float* __restrict__ qh,
                             const float* __restrict__ qr) {
    const size_t n4 = (size_t)L_DIM * D_DIM / 4;
    const float4* a4 = (const float4*)qh;
    const float4* b4 = (const float4*)qr;

    float s = 0.0f;
    for (size_t idx = (size_t)blockIdx.x * blockDim.x + threadIdx.x;
         idx < n4; idx += (size_t)gridDim.x * blockDim.x) {
        float4 a = a4[idx];
        float4 b = b4[idx];
        s += a.x * b.x + a.y * b.y + a.z * b.z + a.w * b.w;
    }
    for (int o = 16; o > 0; o >>= 1) s += __shfl_down_sync(0xffffffffu, s, o);

    __shared__ double red[8];
    int t = threadIdx.x;
    if ((t & 31) == 0) red[t >> 5] = (double)s;
    __syncthreads();
    if (t == 0) {
        double tot = 0.0;
        #pragma unroll
        for (int w = 0; w < 8; w++) tot += red[w];
        atomicAdd(&g_local_sum, tot);
    }
}

// ---------------------------------------------------------------------------
// fp16 mma.sync NT-GEMM (scores = pred @ gt^T) + hinge + global reduce
// + fused finalize in the last-finishing CTA.
// CTA 128(i) x 128(j). BK=64 halfs (128B rows, XOR-16B swizzle).
// 256 threads: 8 warps in 2x4 grid -> 64x32 warp tile, 64 accum/thread.
// 3-stage cp.async (96 KB) -> 2 CTAs/SM; 1024 CTAs smooth the tail.
// ---------------------------------------------------------------------------
#define TM 128
#define TN 128
#define BKH 64                                 // halfs per k-slab (128 B)
#define STAGE_A_BYTES (TM * 128)               // 16 KB
#define STAGE_B_BYTES (TN * 128)               // 16 KB
#define STAGE_BYTES   (STAGE_A_BYTES + STAGE_B_BYTES)
#define NSTAGE 3
#define DYN_SMEM (NSTAGE * STAGE_BYTES + 1024)
#define NKITERS (D_DIM / BKH)                  // 16
#define NCTAS ((B_DIM / TM) * (B_DIM / TN))    // 1024

__device__ __forceinline__ void load_stage(uint32_t aBase, uint32_t bBase,
                                           const __half* __restrict__ predh,
                                           const __half* __restrict__ gth,
                                           int rowA0, int rowB0, int k0, int t) {
    // A: 128 rows x 8 chunks(16B = 8 halfs) = 1024 chunks, 4/thread
    #pragma unroll
    for (int q = 0; q < 4; q++) {
        int idx = t + 256 * q;
        int row = idx >> 3;
        int c   = idx & 7;
        const __half* src = predh + (size_t)(rowA0 + row) * D_DIM + k0 + c * 8;
        uint32_t dst = aBase + row * 128 + ((c ^ (row & 7)) << 4);
        cp_async16(dst, src);
    }
    // B: 128 rows x 8 chunks = 1024 chunks, 4/thread
    #pragma unroll
    for (int q = 0; q < 4; q++) {
        int idx = t + 256 * q;
        int row = idx >> 3;
        int c   = idx & 7;
        const __half* src = gth + (size_t)(rowB0 + row) * D_DIM + k0 + c * 8;
        uint32_t dst = bBase + row * 128 + ((c ^ (row & 7)) << 4);
        cp_async16(dst, src);
    }
}

__global__ __launch_bounds__(256, 2)
void gemm_hinge_mma(float* __restrict__ out) {
    extern __shared__ char dyn[];
    __shared__ double redsm[8];

    const __half* predh = g_pred_h;
    const __half* gth   = g_gt_h;

    const int t    = threadIdx.x;
    const int wid  = t >> 5;
    const int lane = t & 31;
    const int wm   = wid & 1;    // warp row (2) -> 64 rows each
    const int wn   = wid >> 1;   // warp col (4) -> 32 cols each
    const int tg   = lane >> 2;  // groupID 0..7
    const int rowA0 = blockIdx.y * TM;   // pred rows (i)
    const int rowB0 = blockIdx.x * TN;   // gt rows   (j)

    const uint32_t dyn_base = (smem_u32(dyn) + 1023u) & ~1023u;

    // ldmatrix per-thread geometry: tile = lane>>3, tile-row = lane&7.
    const int trow = lane & 7;
    const int tlLo = (lane >> 3) & 1;   // tile&1
    const int tlHi = (lane >> 4) & 1;   // tile>>1
    // A x4 (mf): tiles {r,ch0},{r+8,ch0},{r,ch1},{r+8,ch1}  (= a0..a3 of k16)
    int arow[4], axor[4];
    #pragma unroll
    for (int mf = 0; mf < 4; mf++) {
        int r = wm * 64 + mf * 16 + tlLo * 8 + trow;
        arow[mf] = r * 128;
        axor[mf] = r & 7;
    }
    const int aCadd = tlHi;
    // B x4 (nf pair p): tiles {n,ch0},{n,ch1},{n+8,ch0},{n+8,ch1}
    int brow[2], bxor[2];
    #pragma unroll
    for (int p = 0; p < 2; p++) {
        int r = wn * 32 + p * 16 + tlHi * 8 + trow;
        brow[p] = r * 128;
        bxor[p] = r & 7;
    }
    const int bCadd = tlLo;

    float c[4][4][4];
    #pragma unroll
    for (int mf = 0; mf < 4; mf++)
        #pragma unroll
        for (int nf = 0; nf < 4; nf++)
            #pragma unroll
            for (int r = 0; r < 4; r++) c[mf][nf][r] = 0.0f;

    // Prologue: prefetch stages 0, 1.
    load_stage(dyn_base,               dyn_base + STAGE_A_BYTES,
               predh, gth, rowA0, rowB0, 0, t);
    cp_commit();
    load_stage(dyn_base + STAGE_BYTES, dyn_base + STAGE_BYTES + STAGE_A_BYTES,
               predh, gth, rowA0, rowB0, BKH, t);
    cp_commit();

    for (int it = 0; it < NKITERS; ++it) {
        const uint32_t aBase = dyn_base + (it % NSTAGE) * STAGE_BYTES;
        const uint32_t bBase = aBase + STAGE_A_BYTES;

        if (it < NKITERS - 1) cp_wait1(); else cp_wait0();
        __syncthreads();  // stage `it` visible to all; stage (it+2)%3 free

        if (it + 2 < NKITERS) {
            const uint32_t la = dyn_base + ((it + 2) % NSTAGE) * STAGE_BYTES;
            load_stage(la, la + STAGE_A_BYTES, predh, gth, rowA0, rowB0,
                       (it + 2) * BKH, t);
            cp_commit();
        }

        // 4 k-steps of 16 halfs (2 chunks of 16B each)
        #pragma unroll
        for (int ks = 0; ks < 4; ks++) {
            uint32_t a[4][4];
            #pragma unroll
            for (int mf = 0; mf < 4; mf++) {
                int ch = 2 * ks + aCadd;
                ldsm4(a[mf], aBase + arow[mf] + ((ch ^ axor[mf]) << 4));
            }
            uint32_t b[2][4];  // b[p] = {b0(nf=2p), b1(nf=2p), b0(2p+1), b1(2p+1)}
            #pragma unroll
            for (int p = 0; p < 2; p++) {
                int ch = 2 * ks + bCadd;
                ldsm4(b[p], bBase + brow[p] + ((ch ^ bxor[p]) << 4));
            }
            #pragma unroll
            for (int mf = 0; mf < 4; mf++)
                #pragma unroll
                for (int nf = 0; nf < 4; nf++)
                    mma_f16(c[mf][nf], a[mf], b[nf >> 1] + (nf & 1) * 2);
        }
    }

    // Hinge epilogue straight from register accumulators.
    double acc = 0.0;
    #pragma unroll
    for (int mf = 0; mf < 4; mf++) {
        int r0 = rowA0 + wm * 64 + mf * 16 + tg;
        float p0 = 1.0f - g_pos[r0];
        float p1 = 1.0f - g_pos[r0 + 8];
        #pragma unroll
        for (int nf = 0; nf < 4; nf++) {
            float v0 = c[mf][nf][0] + p0;
            float v1 = c[mf][nf][1] + p0;
            float v2 = c[mf][nf][2] + p1;
            float v3 = c[mf][nf][3] + p1;
            if (v0 > 0.0f) acc += (double)v0;
            if (v1 > 0.0f) acc += (double)v1;
            if (v2 > 0.0f) acc += (double)v2;
            if (v3 > 0.0f) acc += (double)v3;
        }
    }

    for (int o = 16; o > 0; o >>= 1)
        acc += __shfl_down_sync(0xffffffffu, acc, o);
    if (lane == 0) redsm[wid] = acc;
    __syncthreads();
    if (t == 0) {
        double tot = 0.0;
        #pragma unroll
        for (int w = 0; w < 8; w++) tot += redsm[w];
        atomicAdd(&g_glob_sum, tot);
        __threadfence();
        unsigned int done = atomicAdd(&g_done_ctas, 1u);
        if (done == NCTAS - 1) {
            // All other CTAs' g_glob_sum adds are fence-ordered before their
            // counter increments; local_kernel finished before this launch.
            __threadfence();
            out[0] = (float)(g_glob_sum - g_local_sum / (double)L_DIM);
        }
    }
}

// ---------------------------------------------------------------------------
extern "C" void kernel_launch(void* const* d_in, const int* in_sizes, int n_in,
                              void* d_out, int out_size) {
    (void)in_sizes; (void)n_in; (void)out_size;
    const float* q_hat  = (const float*)d_in[0];
    const float* q_real = (const float*)d_in[1];
    const float* gt     = (const float*)d_in[2];  // encoded_gt   [B, D]
    const float* pred   = (const float*)d_in[3];  // encoded_pred [B, D]
    float* out = (float*)d_out;

    cudaFuncSetAttribute(gemm_hinge_mma,
                         cudaFuncAttributeMaxDynamicSharedMemorySize, DYN_SMEM);

    prep_kernel<<<B_DIM, 256>>>(pred, gt);        // init + convert + pos, fused
    local_kernel<<<2048, 256>>>(q_hat, q_real);
    dim3 grid(B_DIM / TN, B_DIM / TM);  // (32 j-tiles, 32 i-tiles)
    gemm_hinge_mma<<<grid, 256, DYN_SMEM>>>(out); // finalize fused in last CTA
}